// round 9
// baseline (speedup 1.0000x reference)
#include <cuda_runtime.h>
#include <cuda_bf16.h>
#include <cstdint>

// ---------------- Problem constants ----------------
#define BDIM 128
#define HDIM 4
#define WDIM 64
#define CDIM 16
#define FEAT (HDIM*WDIM*CDIM)   // 4096

// Output layout (floats): [sat 524288][grd 524288][distance 16384 (g,s)][orien 16384 (s,g)]
#define OFF_SAT   0
#define OFF_GRD   (BDIM*FEAT)
#define OFF_DIST  (2*BDIM*FEAT)
#define OFF_OR    (2*BDIM*FEAT + BDIM*BDIM)

// satC: per s, rows cr=c*4+h (64 rows) of w'=0..126. k = cr*64 + kw.
#define SATC_PER_S 8128
#define ROW_W 127

// ---------------- Static device scratch ----------------
__device__ float g_satCH[BDIM*SATC_PER_S];
__device__ float g_satCL[BDIM*SATC_PER_S];
// grd pre-transposed + (k,k+4) pair-interleaved:
// float idx = ((ch*16 + row)*256) + g*2 + half;  row=q8*4+r; kw = q8*8+r+half*4; k=ch*32+kw
__device__ float g_grdH2[4096*BDIM];
__device__ float g_grdL2[4096*BDIM];
__device__ float g_norms[BDIM];

// ---------------- SMEM layout ----------------
constexpr int A_FLOATS = 2*SATC_PER_S;        // 16256 (Ah + Al)
constexpr int TERM     = 16*264;              // 4224 floats: 16 rows x (128 pairs + 4 pad pairs)
constexpr int BUFF     = 2*TERM;              // 8448 floats per chunk buffer (hi+lo)
constexpr int SMEM_BYTES = (A_FLOATS + 3*BUFF)*4;   // 166400 B

// ---------------- PTX helpers (sm_80-baseline only) ----------------
__device__ __forceinline__ void cp16(float* smem_dst, const float* gsrc) {
    unsigned sa = (unsigned)__cvta_generic_to_shared(smem_dst);
    asm volatile("cp.async.cg.shared.global [%0], [%1], 16;\n" :: "r"(sa), "l"(gsrc));
}
#define CP_COMMIT() asm volatile("cp.async.commit_group;\n" ::: "memory")
#define CP_WAIT0()  asm volatile("cp.async.wait_group 0;\n" ::: "memory")
#define CP_WAIT1()  asm volatile("cp.async.wait_group 1;\n" ::: "memory")

__device__ __forceinline__ float tf32r(float x) {
    unsigned r;
    asm("cvt.rna.tf32.f32 %0, %1;" : "=r"(r) : "f"(x));
    return __uint_as_float(r);
}
__device__ __forceinline__ void mma8(float* d, const unsigned* a, const unsigned* b) {
    asm("mma.sync.aligned.m16n8k8.row.col.f32.tf32.tf32.f32 "
        "{%0,%1,%2,%3},{%4,%5,%6,%7},{%8,%9},{%0,%1,%2,%3};"
        : "+f"(d[0]), "+f"(d[1]), "+f"(d[2]), "+f"(d[3])
        : "r"(a[0]), "r"(a[1]), "r"(a[2]), "r"(a[3]), "r"(b[0]), "r"(b[1]));
}

// ---------------- Pre-kernels ----------------
__global__ void satsplit_kernel(const float* __restrict__ sat) {
    int i = blockIdx.x * 256 + threadIdx.x;
    if (i >= BDIM*SATC_PER_S) return;
    int s  = i / SATC_PER_S;
    int r  = i - s*SATC_PER_S;
    int c  = r / (HDIM*ROW_W);
    int r2 = r - c*(HDIM*ROW_W);
    int h  = r2 / ROW_W;
    int wp = r2 - h*ROW_W;
    int w  = (wp < WDIM) ? wp : wp - WDIM;
    float v  = __ldg(&sat[((s*HDIM + h)*WDIM + w)*CDIM + c]);
    float hi = __uint_as_float(__float_as_uint(v) & 0xFFFFE000u);
    g_satCH[i] = hi;
    g_satCL[i] = tf32r(v - hi);
}
// Pair-interleaved transposed grd + echo (bijective element map)
__global__ void grdsplit_kernel(const float* __restrict__ grd, float* __restrict__ grd_echo) {
    int i = blockIdx.x * 256 + threadIdx.x;   // 0..524287
    int half = i & 1;
    int g    = (i >> 1) & 127;
    int row  = (i >> 8) & 15;
    int ch   = i >> 12;
    int q8 = row >> 2, rr = row & 3;
    int kg = ch*32 + q8*8 + rr + half*4;
    int c  = kg >> 8, h = (kg >> 6) & 3, kwf = kg & 63;
    int src = ((g*HDIM + h)*WDIM + kwf)*CDIM + c;
    float v  = __ldg(&grd[src]);
    float hi = __uint_as_float(__float_as_uint(v) & 0xFFFFE000u);
    g_grdH2[i] = hi;
    g_grdL2[i] = tf32r(v - hi);
    grd_echo[src] = v;
}
__global__ void norms_kernel(const float* __restrict__ sat, float* __restrict__ sat_echo) {
    __shared__ float sw[8];
    int s = blockIdx.x, t = threadIdx.x;
    float ss = 0.f;
    for (int i = t; i < FEAT; i += 256) {
        float v = __ldg(&sat[s*FEAT + i]);
        sat_echo[s*FEAT + i] = v;
        ss += v*v;
    }
    #pragma unroll
    for (int o = 16; o > 0; o >>= 1) ss += __shfl_down_sync(0xffffffffu, ss, o);
    if ((t & 31) == 0) sw[t >> 5] = ss;
    __syncthreads();
    if (t == 0) {
        float tot = 0.f;
        #pragma unroll
        for (int i = 0; i < 8; ++i) tot += sw[i];
        g_norms[s] = fmaxf(sqrtf(tot), 1e-12f);
    }
}

// ---------------- Main kernel: block per s, 512 threads = 16 warps ----------------
// warp w: mrow=(w&1)*32 (j), ncol=((w>>1)&3)*32 (g), kh=w>>3 (k-half of each chunk).
// 128 chunks of k32; warp computes its k16 half (2 k8 steps). 3-buffer cp.async ring.
__global__ __launch_bounds__(512, 1)
void corr_mma_kernel(float* __restrict__ dist, float* __restrict__ orien)
{
    extern __shared__ float smem[];
    float* Ah   = smem;
    float* Al   = smem + SATC_PER_S;
    float* bufs = smem + A_FLOATS;

    const int s  = blockIdx.x;
    const int t  = threadIdx.x;
    const int w  = t >> 5;
    const int l  = t & 31;
    const int mrow = (w & 1) * 32;
    const int ncol = ((w >> 1) & 3) * 32;
    const int kh   = w >> 3;

    const int alane  = (l >> 2) + (l & 3);
    const int blane2 = (ncol + (l >> 2)) * 2;

    // ---- stage A (once) + chunks 0,1 ----
    {
        const float* aH = g_satCH + s*SATC_PER_S;
        const float* aL = g_satCL + s*SATC_PER_S;
        #pragma unroll
        for (int i = 0; i < 8; ++i) {
            int idx = i*512 + t;
            if (idx < 4064) {
                int term = (idx >= 2032);
                int u = idx - term*2032;
                cp16((term ? Al : Ah) + u*4, (term ? aL : aH) + u*4);
            }
        }
    }
    auto stageB = [&](int ch, float* dstbuf) {
        #pragma unroll
        for (int i = 0; i < 4; ++i) {
            int idx = i*512 + t;                  // 2048 = 2 terms x 16 rows x 64 units
            int term = idx >> 10;
            int ru = idx & 1023;
            int row = ru >> 6, u = ru & 63;
            const float* src = (term ? g_grdL2 : g_grdH2) + ch*4096 + row*256 + u*4;
            cp16(dstbuf + term*TERM + row*264 + u*4, src);
        }
    };
    stageB(0, bufs);            CP_COMMIT();   // group: A + chunk0
    stageB(1, bufs + BUFF);     CP_COMMIT();

    float acc[2][4][4];
    #pragma unroll
    for (int f = 0; f < 2; ++f)
        #pragma unroll
        for (int n = 0; n < 4; ++n)
            #pragma unroll
            for (int r = 0; r < 4; ++r) acc[f][n][r] = 0.f;

    for (int ch = 0; ch < 128; ++ch) {
        if (ch == 127) { CP_WAIT0(); } else { CP_WAIT1(); }   // chunk ch landed
        __syncthreads();    // data visible to all; buffer (ch+2)%3 readers (chunk ch-1) done
        if (ch + 2 < 128) { stageB(ch + 2, bufs + ((ch + 2) % 3)*BUFF); CP_COMMIT(); }

        const float* bm = bufs + (ch % 3)*BUFF;
        const int abase = (ch >> 1)*ROW_W + (ch & 1)*32 + kh*16 + mrow + alane;

        #pragma unroll
        for (int q = 0; q < 2; ++q) {
            unsigned ah[8], al8[8], bhf[8], blf[8];
            const int ai = abase + 8*q;
            #pragma unroll
            for (int f = 0; f < 2; ++f) {
                ah[f*4+0] = __float_as_uint(Ah[ai + f*16     ]);
                ah[f*4+1] = __float_as_uint(Ah[ai + f*16 +  8]);
                ah[f*4+2] = __float_as_uint(Ah[ai + f*16 +  4]);
                ah[f*4+3] = __float_as_uint(Ah[ai + f*16 + 12]);
                al8[f*4+0] = __float_as_uint(Al[ai + f*16     ]);
                al8[f*4+1] = __float_as_uint(Al[ai + f*16 +  8]);
                al8[f*4+2] = __float_as_uint(Al[ai + f*16 +  4]);
                al8[f*4+3] = __float_as_uint(Al[ai + f*16 + 12]);
            }
            // B: one LDS.64 per n8 tile per term -> both frag regs {k, k+4}
            const float* bp = bm + ((kh*2 + q)*4 + (l & 3))*264 + blane2;
            #pragma unroll
            for (int n = 0; n < 4; ++n) {
                unsigned long long wh = *(const unsigned long long*)(bp + n*16);
                unsigned long long wl = *(const unsigned long long*)(bp + TERM + n*16);
                bhf[n*2] = (unsigned)wh; bhf[n*2+1] = (unsigned)(wh >> 32);
                blf[n*2] = (unsigned)wl; blf[n*2+1] = (unsigned)(wl >> 32);
            }
            #pragma unroll
            for (int n = 0; n < 4; ++n) {
                mma8(acc[0][n], ah,      bhf + n*2);   // hi*hi
                mma8(acc[1][n], ah + 4,  bhf + n*2);
                mma8(acc[0][n], ah,      blf + n*2);   // hi*lo
                mma8(acc[1][n], ah + 4,  blf + n*2);
                mma8(acc[0][n], al8,     bhf + n*2);   // lo*hi
                mma8(acc[1][n], al8 + 4, bhf + n*2);
            }
        }
    }
    __syncthreads();

    // ---- epilogue: combine kh halves in smem corr[g][j], argmax over j ----
    float* corr_s = bufs;                       // 128*65 floats
    if (kh == 0) {
        #pragma unroll
        for (int f = 0; f < 2; ++f)
            #pragma unroll
            for (int n = 0; n < 4; ++n) {
                const int j = mrow + f*16 + (l >> 2);
                const int g = ncol + n*8 + (l & 3)*2;
                corr_s[(g  )*65 + j    ] = acc[f][n][0];
                corr_s[(g+1)*65 + j    ] = acc[f][n][1];
                corr_s[(g  )*65 + j + 8] = acc[f][n][2];
                corr_s[(g+1)*65 + j + 8] = acc[f][n][3];
            }
    }
    __syncthreads();
    if (kh == 1) {
        #pragma unroll
        for (int f = 0; f < 2; ++f)
            #pragma unroll
            for (int n = 0; n < 4; ++n) {
                const int j = mrow + f*16 + (l >> 2);
                const int g = ncol + n*8 + (l & 3)*2;
                corr_s[(g  )*65 + j    ] += acc[f][n][0];
                corr_s[(g+1)*65 + j    ] += acc[f][n][1];
                corr_s[(g  )*65 + j + 8] += acc[f][n][2];
                corr_s[(g+1)*65 + j + 8] += acc[f][n][3];
            }
    }
    __syncthreads();
    if (t < 128) {
        const int g = t;
        const float* row = corr_s + g*65;
        float bv = row[0]; int bj = 0;
        #pragma unroll
        for (int j = 1; j < 64; ++j) {
            float v = row[j];
            if (v > bv) { bv = v; bj = j; }     // strict > : earliest j (jnp.argmax)
        }
        orien[s*BDIM + g] = (float)bj;
        dist[g*BDIM + s]  = 2.0f - 2.0f * (bv / g_norms[s]);
    }
}

// ---------------- Launcher ----------------
extern "C" void kernel_launch(void* const* d_in, const int* in_sizes, int n_in,
                              void* d_out, int out_size)
{
    const float* sat = (const float*)d_in[0];
    const float* grd = (const float*)d_in[1];
    float* out = (float*)d_out;

    satsplit_kernel<<<(BDIM*SATC_PER_S + 255)/256, 256>>>(sat);
    grdsplit_kernel<<<(4096*BDIM)/256, 256>>>(grd, out + OFF_GRD);  // + grd echo
    norms_kernel<<<BDIM, 256>>>(sat, out + OFF_SAT);                // + sat echo

    cudaFuncSetAttribute(corr_mma_kernel,
                         cudaFuncAttributeMaxDynamicSharedMemorySize, SMEM_BYTES);
    corr_mma_kernel<<<BDIM, 512, SMEM_BYTES>>>(out + OFF_DIST, out + OFF_OR);
}

// round 11
// speedup vs baseline: 1.1482x; 1.1482x over previous
#include <cuda_runtime.h>
#include <cuda_bf16.h>
#include <cstdint>

// ---------------- Problem constants ----------------
#define BDIM 128
#define HDIM 4
#define WDIM 64
#define CDIM 16
#define FEAT (HDIM*WDIM*CDIM)   // 4096

// Output layout (floats): [sat 524288][grd 524288][distance 16384 (g,s)][orien 16384 (s,g)]
#define OFF_SAT   0
#define OFF_GRD   (BDIM*FEAT)
#define OFF_DIST  (2*BDIM*FEAT)
#define OFF_OR    (2*BDIM*FEAT + BDIM*BDIM)

// satC: per s, rows cr=c*4+h (64 rows) of w'=0..126. k = cr*64 + kw.
#define SATC_PER_S 8128
#define ROW_W 127

// ---------------- Static device scratch ----------------
__device__ float g_satCH[BDIM*SATC_PER_S];
__device__ float g_satCL[BDIM*SATC_PER_S];
// grd transposed + (k,k+4) pair-interleaved, in k32 groups of 16 rows:
// idx = ((ch32*16 + q*4 + r)*256) + g*2 + half;  k = ch32*32 + q*8 + r + half*4
__device__ float g_grdH2[4096*BDIM];
__device__ float g_grdL2[4096*BDIM];
__device__ float g_norms[BDIM];

// ---------------- SMEM layout ----------------
constexpr int A_FLOATS = 2*SATC_PER_S;        // 16256 (Ah + Al)
constexpr int TERM     = 32*264;              // 8448 floats: 32 k-pair rows x (128 g-pairs + pad)
constexpr int BUFF     = 2*TERM;              // 16896 floats per k64 chunk buffer (hi+lo)
constexpr int SMEM_BYTES = (A_FLOATS + 2*BUFF)*4;   // 200192 B

// ---------------- PTX helpers (sm_80-baseline only) ----------------
__device__ __forceinline__ void cp16(float* smem_dst, const float* gsrc) {
    unsigned sa = (unsigned)__cvta_generic_to_shared(smem_dst);
    asm volatile("cp.async.cg.shared.global [%0], [%1], 16;\n" :: "r"(sa), "l"(gsrc));
}
#define CP_COMMIT() asm volatile("cp.async.commit_group;\n" ::: "memory")
#define CP_WAIT0()  asm volatile("cp.async.wait_group 0;\n" ::: "memory")
#define CP_WAIT1()  asm volatile("cp.async.wait_group 1;\n" ::: "memory")

__device__ __forceinline__ float tf32r(float x) {
    unsigned r;
    asm("cvt.rna.tf32.f32 %0, %1;" : "=r"(r) : "f"(x));
    return __uint_as_float(r);
}
__device__ __forceinline__ void mma8(float* d, const unsigned* a, const unsigned* b) {
    asm("mma.sync.aligned.m16n8k8.row.col.f32.tf32.tf32.f32 "
        "{%0,%1,%2,%3},{%4,%5,%6,%7},{%8,%9},{%0,%1,%2,%3};"
        : "+f"(d[0]), "+f"(d[1]), "+f"(d[2]), "+f"(d[3])
        : "r"(a[0]), "r"(a[1]), "r"(a[2]), "r"(a[3]), "r"(b[0]), "r"(b[1]));
}

// ---------------- Pre-kernels ----------------
// Merged: satsplit (first 1040384 ids) + grdsplit w/ echo (next 524288 ids)
__global__ void split_kernel(const float* __restrict__ sat,
                             const float* __restrict__ grd,
                             float* __restrict__ grd_echo)
{
    int i = blockIdx.x * 256 + threadIdx.x;
    if (i < BDIM*SATC_PER_S) {
        int s  = i / SATC_PER_S;
        int r  = i - s*SATC_PER_S;
        int c  = r / (HDIM*ROW_W);
        int r2 = r - c*(HDIM*ROW_W);
        int h  = r2 / ROW_W;
        int wp = r2 - h*ROW_W;
        int w  = (wp < WDIM) ? wp : wp - WDIM;      // circular extension
        float v  = __ldg(&sat[((s*HDIM + h)*WDIM + w)*CDIM + c]);
        float hi = __uint_as_float(__float_as_uint(v) & 0xFFFFE000u);
        g_satCH[i] = hi;
        g_satCL[i] = tf32r(v - hi);
    } else {
        int j = i - BDIM*SATC_PER_S;
        if (j < 4096*BDIM) {
            int half = j & 1;
            int g    = (j >> 1) & 127;
            int row  = (j >> 8) & 15;
            int ch   = j >> 12;
            int q = row >> 2, rr = row & 3;
            int kg = ch*32 + q*8 + rr + half*4;
            int c  = kg >> 8, h = (kg >> 6) & 3, kwf = kg & 63;
            int src = ((g*HDIM + h)*WDIM + kwf)*CDIM + c;
            float v  = __ldg(&grd[src]);
            float hi = __uint_as_float(__float_as_uint(v) & 0xFFFFE000u);
            g_grdH2[j] = hi;
            g_grdL2[j] = tf32r(v - hi);
            grd_echo[src] = v;
        }
    }
}
__global__ void norms_kernel(const float* __restrict__ sat, float* __restrict__ sat_echo) {
    __shared__ float sw[8];
    int s = blockIdx.x, t = threadIdx.x;
    float ss = 0.f;
    for (int i = t; i < FEAT; i += 256) {
        float v = __ldg(&sat[s*FEAT + i]);
        sat_echo[s*FEAT + i] = v;
        ss += v*v;
    }
    #pragma unroll
    for (int o = 16; o > 0; o >>= 1) ss += __shfl_down_sync(0xffffffffu, ss, o);
    if ((t & 31) == 0) sw[t >> 5] = ss;
    __syncthreads();
    if (t == 0) {
        float tot = 0.f;
        #pragma unroll
        for (int i = 0; i < 8; ++i) tot += sw[i];
        g_norms[s] = fmaxf(sqrtf(tot), 1e-12f);
    }
}

// ---------------- Main kernel: block per s, 256 threads = 8 warps ----------------
// warp w: mrow=(w&1)*32 (j), ncol=(w>>1)*32 (g). Warp tile m32 n32, full K.
// 64 chunks of k64 (one cr row each), 2-buffer cp.async, frag prefetch pipeline.
__global__ __launch_bounds__(256, 1)
void corr_mma_kernel(float* __restrict__ dist, float* __restrict__ orien)
{
    extern __shared__ float smem[];
    float* Ah   = smem;
    float* Al   = smem + SATC_PER_S;
    float* bufs = smem + A_FLOATS;

    const int s  = blockIdx.x;
    const int t  = threadIdx.x;
    const int w  = t >> 5;
    const int l  = t & 31;
    const int mrow = (w & 1) * 32;
    const int ncol = (w >> 1) * 32;

    const int alane  = (l >> 2) + (l & 3);
    const int blane2 = (ncol + (l >> 2)) * 2;

    // ---- stage A (once) ----
    {
        const float* aH = g_satCH + s*SATC_PER_S;
        const float* aL = g_satCL + s*SATC_PER_S;
        #pragma unroll
        for (int i = 0; i < 16; ++i) {
            int idx = i*256 + t;
            if (idx < 4064) {
                int term = (idx >= 2032);
                int u = idx - term*2032;
                cp16((term ? Al : Ah) + u*4, (term ? aL : aH) + u*4);
            }
        }
    }
    // stage one k64 chunk (= 32 contiguous interleaved rows per term)
    auto stageB = [&](int ch, float* dstbuf) {
        #pragma unroll
        for (int i = 0; i < 16; ++i) {
            int idx = i*256 + t;                 // 4096 = 2 terms x 32 rows x 64 units
            int term = idx >> 11;
            int ru = idx & 2047;
            int row = ru >> 6, u = ru & 63;
            const float* src = (term ? g_grdL2 : g_grdH2) + ch*8192 + row*256 + u*4;
            cp16(dstbuf + term*TERM + row*264 + u*4, src);
        }
    };
    stageB(0, bufs);        CP_COMMIT();        // group: A + chunk0
    stageB(1, bufs + BUFF); CP_COMMIT();

    float acc[2][4][4];
    #pragma unroll
    for (int f = 0; f < 2; ++f)
        #pragma unroll
        for (int n = 0; n < 4; ++n)
            #pragma unroll
            for (int r = 0; r < 4; ++r) acc[f][n][r] = 0.f;

    auto loadA = [&](int ai, unsigned* a8, unsigned* b8) {
        #pragma unroll
        for (int f = 0; f < 2; ++f) {
            a8[f*4+0] = __float_as_uint(Ah[ai + f*16     ]);
            a8[f*4+1] = __float_as_uint(Ah[ai + f*16 +  8]);
            a8[f*4+2] = __float_as_uint(Ah[ai + f*16 +  4]);
            a8[f*4+3] = __float_as_uint(Ah[ai + f*16 + 12]);
            b8[f*4+0] = __float_as_uint(Al[ai + f*16     ]);
            b8[f*4+1] = __float_as_uint(Al[ai + f*16 +  8]);
            b8[f*4+2] = __float_as_uint(Al[ai + f*16 +  4]);
            b8[f*4+3] = __float_as_uint(Al[ai + f*16 + 12]);
        }
    };
    auto loadB = [&](const float* bm, int q, unsigned* h8, unsigned* l8) {
        const float* bp = bm + (q*4 + (l & 3))*264 + blane2;
        #pragma unroll
        for (int n = 0; n < 4; ++n) {
            unsigned long long wh = *(const unsigned long long*)(bp + n*16);
            unsigned long long wl = *(const unsigned long long*)(bp + TERM + n*16);
            h8[n*2] = (unsigned)wh; h8[n*2+1] = (unsigned)(wh >> 32);
            l8[n*2] = (unsigned)wl; l8[n*2+1] = (unsigned)(wl >> 32);
        }
    };

    for (int ch = 0; ch < 64; ++ch) {
        if (ch == 63) { CP_WAIT0(); } else { CP_WAIT1(); }   // chunk ch landed
        __syncthreads();

        const float* bm = bufs + (ch & 1)*BUFF;
        const int abase = ch*ROW_W + mrow + alane;

        unsigned ah[2][8], al8[2][8], bh[2][8], bl[2][8];
        loadA(abase, ah[0], al8[0]);
        loadB(bm, 0, bh[0], bl[0]);

        #pragma unroll
        for (int q = 0; q < 8; ++q) {
            const int cur = q & 1, nxt = cur ^ 1;
            if (q < 7) {                          // prefetch next q's frags during burst
                loadA(abase + 8*(q + 1), ah[nxt], al8[nxt]);
                loadB(bm, q + 1, bh[nxt], bl[nxt]);
            }
            // pass-major: accumulator chains spaced 8 HMMAs apart
            #pragma unroll
            for (int n = 0; n < 4; ++n) {        // hi*hi
                mma8(acc[0][n], ah[cur],     bh[cur] + n*2);
                mma8(acc[1][n], ah[cur] + 4, bh[cur] + n*2);
            }
            #pragma unroll
            for (int n = 0; n < 4; ++n) {        // hi*lo
                mma8(acc[0][n], ah[cur],     bl[cur] + n*2);
                mma8(acc[1][n], ah[cur] + 4, bl[cur] + n*2);
            }
            #pragma unroll
            for (int n = 0; n < 4; ++n) {        // lo*hi
                mma8(acc[0][n], al8[cur],     bh[cur] + n*2);
                mma8(acc[1][n], al8[cur] + 4, bh[cur] + n*2);
            }
        }
        __syncthreads();                          // all warps done with buf(ch&1)
        if (ch + 2 < 64) { stageB(ch + 2, bufs + (ch & 1)*BUFF); CP_COMMIT(); }
    }

    // ---- epilogue: acc -> smem corr[g][j] (pad 65), argmax over j ----
    float* corr_s = bufs;
    #pragma unroll
    for (int f = 0; f < 2; ++f)
        #pragma unroll
        for (int n = 0; n < 4; ++n) {
            const int j = mrow + f*16 + (l >> 2);
            const int g = ncol + n*8 + (l & 3)*2;
            corr_s[(g  )*65 + j    ] = acc[f][n][0];
            corr_s[(g+1)*65 + j    ] = acc[f][n][1];
            corr_s[(g  )*65 + j + 8] = acc[f][n][2];
            corr_s[(g+1)*65 + j + 8] = acc[f][n][3];
        }
    __syncthreads();
    if (t < 128) {
        const int g = t;
        const float* row = corr_s + g*65;
        float bv = row[0]; int bj = 0;
        #pragma unroll
        for (int j = 1; j < 64; ++j) {
            float v = row[j];
            if (v > bv) { bv = v; bj = j; }      // strict > : earliest j (jnp.argmax)
        }
        orien[s*BDIM + g] = (float)bj;
        dist[g*BDIM + s]  = 2.0f - 2.0f * (bv / g_norms[s]);
    }
}

// ---------------- Launcher ----------------
extern "C" void kernel_launch(void* const* d_in, const int* in_sizes, int n_in,
                              void* d_out, int out_size)
{
    const float* sat = (const float*)d_in[0];
    const float* grd = (const float*)d_in[1];
    float* out = (float*)d_out;

    const int total = BDIM*SATC_PER_S + 4096*BDIM;   // merged split work
    split_kernel<<<(total + 255)/256, 256>>>(sat, grd, out + OFF_GRD);
    norms_kernel<<<BDIM, 256>>>(sat, out + OFF_SAT);

    cudaFuncSetAttribute(corr_mma_kernel,
                         cudaFuncAttributeMaxDynamicSharedMemorySize, SMEM_BYTES);
    corr_mma_kernel<<<BDIM, 256, SMEM_BYTES>>>(out + OFF_DIST, out + OFF_OR);
}